// round 1
// baseline (speedup 1.0000x reference)
#include <cuda_runtime.h>
#include <math_constants.h>

#define BB 32
#define SS 480
#define DD 512
#define HH 8
#define DK 64
#define ML 500          // rel_bias row stride (MAX_LEN)
#define QT 32           // query rows per attention CTA
#define JT 128          // key/value tile width
#define QTP 36          // padded stride for q^T tile
#define JTP 132         // padded stride for k^T tile

// Scratch (device globals — no allocations allowed)
__device__ float g_q[BB*HH*SS*DK];
__device__ float g_k[BB*HH*SS*DK];
__device__ float g_v[BB*HH*SS*DK];
__device__ float g_ctx[(size_t)BB*SS*DD];

// ---------------------------------------------------------------------------
// Kernel 1: fused QKV projection.  C = x @ W + b, scattered to [B,H,S,dk].
// 64x64 block tile, BK=16, 256 threads, 4x4 per-thread tile, float4 smem reads.
// ---------------------------------------------------------------------------
__global__ __launch_bounds__(256) void proj_qkv(
    const float* __restrict__ x,
    const float* __restrict__ wq, const float* __restrict__ bq,
    const float* __restrict__ wk, const float* __restrict__ bk,
    const float* __restrict__ wv, const float* __restrict__ bv)
{
    const int z = blockIdx.z;
    const float* W    = (z == 0) ? wq : (z == 1) ? wk : wv;
    const float* bias = (z == 0) ? bq : (z == 1) ? bk : bv;
    float* Out        = (z == 0) ? g_q : (z == 1) ? g_k : g_v;

    __shared__ float Xs[16][68];   // [k][row], padded (bank-spread)
    __shared__ float Ws[16][64];   // [k][col]

    const int m0 = blockIdx.x * 64;
    const int n0 = blockIdx.y * 64;
    const int tid = threadIdx.x;
    const int tx = tid & 15, ty = tid >> 4;

    const int lt = tid & 15, lr = tid >> 4;   // X load: k, row
    const int wc = tid & 63, wt = tid >> 6;   // W load: col, k

    float acc[4][4] = {};

    for (int k0 = 0; k0 < DD; k0 += 16) {
#pragma unroll
        for (int rr = 0; rr < 4; rr++)
            Xs[lt][lr + rr*16] = x[(size_t)(n0 + lr + rr*16)*DD + k0 + lt];
#pragma unroll
        for (int tt = 0; tt < 4; tt++)
            Ws[wt + tt*4][wc] = W[(size_t)(k0 + wt + tt*4)*DD + m0 + wc];
        __syncthreads();
#pragma unroll
        for (int t = 0; t < 16; t++) {
            float4 a4 = *(const float4*)&Xs[t][ty*4];
            float4 b4 = *(const float4*)&Ws[t][tx*4];
            float av[4] = {a4.x, a4.y, a4.z, a4.w};
            float bw[4] = {b4.x, b4.y, b4.z, b4.w};
#pragma unroll
            for (int i = 0; i < 4; i++)
#pragma unroll
                for (int j = 0; j < 4; j++)
                    acc[i][j] += av[i] * bw[j];
        }
        __syncthreads();
    }

#pragma unroll
    for (int i = 0; i < 4; i++) {
        int n = n0 + ty*4 + i;
        int b = n / SS, s = n % SS;
#pragma unroll
        for (int j = 0; j < 4; j++) {
            int m = m0 + tx*4 + j;
            int h = m >> 6, d = m & 63;
            Out[(((size_t)b*HH + h)*SS + s)*DK + d] = acc[i][j] + bias[m];
        }
    }
}

// ---------------------------------------------------------------------------
// Kernel 2: attention.  One CTA per (b, 32-row q tile); loops all 8 heads.
// Scores (with bias + causal mask) materialized in smem, full softmax,
// probs accumulated into attn-mean (no atomics), then P @ V into g_ctx.
// Causal tile skipping: only j < i0+QT tiles are touched.
// ---------------------------------------------------------------------------
__global__ __launch_bounds__(256) void attn_kernel(
    const float* __restrict__ rel_bias, float* __restrict__ out_attn)
{
    extern __shared__ float smem[];
    float* sc  = smem;                       // QT*SS  scores -> probs
    float* am  = sc + QT*SS;                 // QT*SS  attn-mean accumulator
    float* qsT = am + QT*SS;                 // 64*QTP q^T tile
    float* kvb = qsT + 64*QTP;               // 64*JTP K^T  /  JT*64 V

    const int b  = blockIdx.y;
    const int i0 = blockIdx.x * QT;
    const int tid = threadIdx.x;
    const int lane = tid & 31, warp = tid >> 5;

    const int jcount = i0 + QT;                       // exclusive causal bound
    const int ntile  = (jcount + JT - 1) / JT;
    const int jcap   = min(SS, ntile * JT);           // columns with valid sc

    for (int idx = tid; idx < QT*SS; idx += 256) am[idx] = 0.f;

    for (int h = 0; h < HH; h++) {
        const float* qg = g_q + (((size_t)b*HH + h)*SS + i0)*DK;
        const float* kg = g_k + (((size_t)b*HH + h)*SS)*DK;
        const float* vg = g_v + (((size_t)b*HH + h)*SS)*DK;
        __syncthreads();   // previous head fully consumed sc/qsT/kvb

        // load q tile transposed: qsT[t][i]
        for (int idx = tid; idx < QT*DK; idx += 256) {
            int i = idx >> 6, t = idx & 63;
            qsT[t*QTP + i] = qg[idx];
        }

        // ----- scores: S = q k^T / 8 + bias, causal mask -----
        for (int jt = 0; jt < ntile; jt++) {
            int j0 = jt * JT;
            __syncthreads();
            for (int idx = tid; idx < JT*DK; idx += 256) {
                int jl = idx >> 6, t = idx & 63;
                int j = j0 + jl;
                kvb[t*JTP + jl] = (j < SS) ? kg[(size_t)j*DK + t] : 0.f;
            }
            __syncthreads();
            const int ti = (tid >> 5) * 4;       // 8 row groups of 4
            const int tj = (tid & 31) * 4;       // 32 col groups of 4
            float acc[4][4] = {};
#pragma unroll
            for (int t = 0; t < 64; t++) {
                float4 a4 = *(const float4*)&qsT[t*QTP + ti];
                float4 b4 = *(const float4*)&kvb[t*JTP + tj];
                float av[4] = {a4.x, a4.y, a4.z, a4.w};
                float bw[4] = {b4.x, b4.y, b4.z, b4.w};
#pragma unroll
                for (int i = 0; i < 4; i++)
#pragma unroll
                    for (int j = 0; j < 4; j++)
                        acc[i][j] += av[i] * bw[j];
            }
#pragma unroll
            for (int ii = 0; ii < 4; ii++) {
                int i = i0 + ti + ii;
                const float* brow = rel_bias + ((size_t)h*ML + i)*ML;
                float vals[4];
#pragma unroll
                for (int jj = 0; jj < 4; jj++) {
                    int j = j0 + tj + jj;
                    vals[jj] = (j <= i && j < SS) ? acc[ii][jj]*0.125f + brow[j]
                                                  : -CUDART_INF_F;
                }
                if (j0 + JT <= SS) {
                    *(float4*)&sc[(ti+ii)*SS + j0 + tj] =
                        make_float4(vals[0], vals[1], vals[2], vals[3]);
                } else {
#pragma unroll
                    for (int jj = 0; jj < 4; jj++) {
                        int j = j0 + tj + jj;
                        if (j < SS) sc[(ti+ii)*SS + j] = vals[jj];
                    }
                }
            }
        }
        __syncthreads();

        // ----- softmax per row (one warp per 4 rows), accumulate attn mean -----
        for (int r = warp; r < QT; r += 8) {
            float* row = sc + r*SS;
            float m = -CUDART_INF_F;
            for (int j = lane; j < jcap; j += 32) m = fmaxf(m, row[j]);
#pragma unroll
            for (int o = 16; o; o >>= 1) m = fmaxf(m, __shfl_xor_sync(0xffffffffu, m, o));
            float ssum = 0.f;
            for (int j = lane; j < jcap; j += 32) {
                float e = __expf(row[j] - m);
                row[j] = e;
                ssum += e;
            }
#pragma unroll
            for (int o = 16; o; o >>= 1) ssum += __shfl_xor_sync(0xffffffffu, ssum, o);
            float inv = 1.f / ssum;
            float* amrow = am + r*SS;
            for (int j = lane; j < jcap; j += 32) {
                float p = row[j] * inv;
                row[j] = p;
                amrow[j] += p * 0.125f;   // mean over 8 heads
            }
        }
        __syncthreads();

        // ----- ctx = P @ V -----
        {
            const int i = tid >> 3;
            const int dbase = (tid & 7) * 8;
            float acc[8] = {};
            for (int jt = 0; jt < ntile; jt++) {
                int j0 = jt * JT;
                __syncthreads();
                for (int idx = tid; idx < JT*DK; idx += 256) {
                    int j = j0 + (idx >> 6);
                    kvb[idx] = (j < SS) ? vg[(size_t)j*DK + (idx & 63)] : 0.f;
                }
                __syncthreads();
                int jlim = min(JT, jcap - j0);
                for (int jj = 0; jj < jlim; jj++) {
                    float p = sc[i*SS + j0 + jj];
                    float4 v0 = *(const float4*)&kvb[(jj << 6) + dbase];
                    float4 v1 = *(const float4*)&kvb[(jj << 6) + dbase + 4];
                    acc[0] += p*v0.x; acc[1] += p*v0.y; acc[2] += p*v0.z; acc[3] += p*v0.w;
                    acc[4] += p*v1.x; acc[5] += p*v1.y; acc[6] += p*v1.z; acc[7] += p*v1.w;
                }
            }
            float* dst = g_ctx + ((size_t)b*SS + i0 + i)*DD + h*DK + dbase;
#pragma unroll
            for (int u = 0; u < 8; u++) dst[u] = acc[u];
        }
    }

    __syncthreads();
    for (int idx = tid; idx < QT*SS; idx += 256) {
        int i = idx / SS, j = idx % SS;
        out_attn[((size_t)b*SS + i0 + i)*SS + j] = am[idx];
    }
}

// ---------------------------------------------------------------------------
// Kernel 3: output projection.  out = ctx @ wo + bo  (row-major [B*S, D]).
// ---------------------------------------------------------------------------
__global__ __launch_bounds__(256) void out_proj(
    const float* __restrict__ wo, const float* __restrict__ bo,
    float* __restrict__ out)
{
    __shared__ float Xs[16][68];
    __shared__ float Ws[16][64];

    const int m0 = blockIdx.x * 64;
    const int n0 = blockIdx.y * 64;
    const int tid = threadIdx.x;
    const int tx = tid & 15, ty = tid >> 4;

    const int lt = tid & 15, lr = tid >> 4;
    const int wc = tid & 63, wt = tid >> 6;

    float acc[4][4] = {};

    for (int k0 = 0; k0 < DD; k0 += 16) {
#pragma unroll
        for (int rr = 0; rr < 4; rr++)
            Xs[lt][lr + rr*16] = g_ctx[(size_t)(n0 + lr + rr*16)*DD + k0 + lt];
#pragma unroll
        for (int tt = 0; tt < 4; tt++)
            Ws[wt + tt*4][wc] = wo[(size_t)(k0 + wt + tt*4)*DD + m0 + wc];
        __syncthreads();
#pragma unroll
        for (int t = 0; t < 16; t++) {
            float4 a4 = *(const float4*)&Xs[t][ty*4];
            float4 b4 = *(const float4*)&Ws[t][tx*4];
            float av[4] = {a4.x, a4.y, a4.z, a4.w};
            float bw[4] = {b4.x, b4.y, b4.z, b4.w};
#pragma unroll
            for (int i = 0; i < 4; i++)
#pragma unroll
                for (int j = 0; j < 4; j++)
                    acc[i][j] += av[i] * bw[j];
        }
        __syncthreads();
    }

#pragma unroll
    for (int i = 0; i < 4; i++) {
        int n = n0 + ty*4 + i;
#pragma unroll
        for (int j = 0; j < 4; j++) {
            int m = m0 + tx*4 + j;
            out[(size_t)n*DD + m] = acc[i][j] + bo[m];
        }
    }
}

// ---------------------------------------------------------------------------

static const int ATTN_SMEM = (QT*SS*2 + 64*QTP + 64*JTP) * (int)sizeof(float); // 165888

extern "C" void kernel_launch(void* const* d_in, const int* in_sizes, int n_in,
                              void* d_out, int out_size) {
    const float* x  = (const float*)d_in[0];
    const float* wq = (const float*)d_in[1];
    const float* bq = (const float*)d_in[2];
    const float* wk = (const float*)d_in[3];
    const float* bk = (const float*)d_in[4];
    const float* wv = (const float*)d_in[5];
    const float* bv = (const float*)d_in[6];
    const float* wo = (const float*)d_in[7];
    const float* bo = (const float*)d_in[8];
    const float* rb = (const float*)d_in[9];

    float* out      = (float*)d_out;
    float* out_attn = out + (size_t)BB*SS*DD;

    // 1) QKV projections
    proj_qkv<<<dim3(DD/64, (BB*SS)/64, 3), 256>>>(x, wq, bq, wk, bk, wv, bv);

    // 2) attention (idempotent attribute set; host-side, capture-safe)
    cudaFuncSetAttribute(attn_kernel, cudaFuncAttributeMaxDynamicSharedMemorySize, ATTN_SMEM);
    attn_kernel<<<dim3(SS/QT, BB), 256, ATTN_SMEM>>>(rb, out_attn);

    // 3) output projection
    out_proj<<<dim3(DD/64, (BB*SS)/64), 256>>>(wo, bo, out);
}

// round 2
// speedup vs baseline: 1.4410x; 1.4410x over previous
#include <cuda_runtime.h>
#include <math_constants.h>

#define BB 32
#define SS 480
#define DD 512
#define HH 8
#define DK 64
#define ML 500          // rel_bias row stride (MAX_LEN)
#define QT 32           // query rows per attention CTA
#define JT 128          // key/value tile width
#define QTP 36          // padded stride for q^T tile
#define JTP 132         // padded stride for k^T tile

// Scratch (device globals — no allocations allowed)
__device__ float g_q[BB*HH*SS*DK];
__device__ float g_k[BB*HH*SS*DK];
__device__ float g_v[BB*HH*SS*DK];
__device__ float g_ctx[(size_t)BB*SS*DD];

// ---------------------------------------------------------------------------
// Kernel 1: fused QKV projection.  C = x @ W + b, scattered to [B,H,S,dk].
// 128(rows) x 64(cols) tile, BK=32, 256 threads, 8x4 per-thread tile.
// ---------------------------------------------------------------------------
__global__ __launch_bounds__(256) void proj_qkv(
    const float* __restrict__ x,
    const float* __restrict__ wq, const float* __restrict__ bq,
    const float* __restrict__ wk, const float* __restrict__ bk,
    const float* __restrict__ wv, const float* __restrict__ bv)
{
    const int z = blockIdx.z;
    const float* W    = (z == 0) ? wq : (z == 1) ? wk : wv;
    const float* bias = (z == 0) ? bq : (z == 1) ? bk : bv;
    float* Out        = (z == 0) ? g_q : (z == 1) ? g_k : g_v;

    __shared__ float Xs[32][132];   // [k][row]
    __shared__ float Ws[32][68];    // [k][col]

    const int m0 = blockIdx.x * 64;    // output col tile (one head block)
    const int n0 = blockIdx.y * 128;   // output row tile
    const int tid = threadIdx.x;

    // X load: float4 per row-chunk. c8 = which float4 of the 32-k row, r = row
    const int c8 = tid & 7, xr = tid >> 3;       // xr 0..31
    // W load: wc = col, wt = k base
    const int wc = tid & 63, wt = tid >> 6;      // wt 0..3
    // compute map: ri -> 8 rows, ci -> 4 cols
    const int ri = tid >> 4, ci = tid & 15;

    float acc[8][4] = {};

    for (int k0 = 0; k0 < DD; k0 += 32) {
#pragma unroll
        for (int rr = 0; rr < 4; rr++) {
            int r = xr + rr*32;
            float4 v = *(const float4*)&x[(size_t)(n0 + r)*DD + k0 + c8*4];
            Xs[c8*4+0][r] = v.x; Xs[c8*4+1][r] = v.y;
            Xs[c8*4+2][r] = v.z; Xs[c8*4+3][r] = v.w;
        }
#pragma unroll
        for (int tt = 0; tt < 8; tt++)
            Ws[wt + tt*4][wc] = W[(size_t)(k0 + wt + tt*4)*DD + m0 + wc];
        __syncthreads();
#pragma unroll
        for (int t = 0; t < 32; t++) {
            float4 a0 = *(const float4*)&Xs[t][ri*8];
            float4 a1 = *(const float4*)&Xs[t][ri*8+4];
            float4 b4 = *(const float4*)&Ws[t][ci*4];
            float av[8] = {a0.x,a0.y,a0.z,a0.w,a1.x,a1.y,a1.z,a1.w};
            float bw[4] = {b4.x,b4.y,b4.z,b4.w};
#pragma unroll
            for (int i = 0; i < 8; i++)
#pragma unroll
                for (int j = 0; j < 4; j++)
                    acc[i][j] += av[i] * bw[j];
        }
        __syncthreads();
    }

    const float4 bb = *(const float4*)&bias[m0 + ci*4];
    const int h = m0 >> 6;
    const int dbase = ci*4;
#pragma unroll
    for (int u = 0; u < 8; u++) {
        int n = n0 + ri*8 + u;
        int b = n / SS, s = n % SS;
        float4 o = make_float4(acc[u][0]+bb.x, acc[u][1]+bb.y,
                               acc[u][2]+bb.z, acc[u][3]+bb.w);
        *(float4*)&Out[(((size_t)b*HH + h)*SS + s)*DK + dbase] = o;
    }
}

// ---------------------------------------------------------------------------
// Kernel 2: attention.  One CTA per (b, 32-row q tile); loops all 8 heads.
// 512 threads. attn-mean accumulated into gmem (L2-resident) so smem fits
// 2 CTAs/SM (100% occupancy). Causal tile skipping.
// ---------------------------------------------------------------------------
__global__ __launch_bounds__(512, 2) void attn_kernel(
    const float* __restrict__ rel_bias, float* __restrict__ out_attn)
{
    extern __shared__ float smem[];
    float* sc  = smem;                       // QT*SS  scores -> probs
    float* qsT = sc + QT*SS;                 // 64*QTP q^T tile
    float* kvb = qsT + 64*QTP;               // 64*JTP K^T  /  JT*64 V

    const int b  = blockIdx.y;
    const int i0 = blockIdx.x * QT;
    const int tid = threadIdx.x;
    const int lane = tid & 31, warp = tid >> 5;

    const int jcount = i0 + QT;                       // exclusive causal bound
    const int ntile  = (jcount + JT - 1) / JT;
    const int jcap   = min(SS, ntile * JT);

    const size_t abase = ((size_t)b*SS + i0)*SS;

    for (int h = 0; h < HH; h++) {
        const float* qg = g_q + (((size_t)b*HH + h)*SS + i0)*DK;
        const float* kg = g_k + (((size_t)b*HH + h)*SS)*DK;
        const float* vg = g_v + (((size_t)b*HH + h)*SS)*DK;
        __syncthreads();   // previous head fully consumed sc/qsT/kvb

        // load q tile transposed: qsT[t][i]
        for (int idx = tid; idx < QT*DK; idx += 512) {
            int i = idx >> 6, t = idx & 63;
            qsT[t*QTP + i] = qg[idx];
        }

        // ----- scores: S = q k^T / 8 + bias, causal mask -----
        for (int jt = 0; jt < ntile; jt++) {
            int j0 = jt * JT;
            __syncthreads();
            for (int idx = tid; idx < JT*DK; idx += 512) {
                int jl = idx >> 6, t = idx & 63;
                int j = j0 + jl;
                kvb[t*JTP + jl] = (j < SS) ? kg[(size_t)j*DK + t] : 0.f;
            }
            __syncthreads();
            const int ig = tid >> 6;          // 8 groups of 4 rows
            const int jg = tid & 63;          // 64 groups of 2 cols
            float acc[4][2] = {};
#pragma unroll
            for (int t = 0; t < 64; t++) {
                float4 a4 = *(const float4*)&qsT[t*QTP + ig*4];
                float2 b2 = *(const float2*)&kvb[t*JTP + jg*2];
                float av[4] = {a4.x, a4.y, a4.z, a4.w};
#pragma unroll
                for (int i = 0; i < 4; i++) {
                    acc[i][0] += av[i] * b2.x;
                    acc[i][1] += av[i] * b2.y;
                }
            }
#pragma unroll
            for (int ii = 0; ii < 4; ii++) {
                int i = i0 + ig*4 + ii;
                const float* brow = rel_bias + ((size_t)h*ML + i)*ML;
                float v0, v1;
                int j0c = j0 + jg*2;
                v0 = (j0c   <= i && j0c   < SS) ? acc[ii][0]*0.125f + brow[j0c]   : -CUDART_INF_F;
                v1 = (j0c+1 <= i && j0c+1 < SS) ? acc[ii][1]*0.125f + brow[j0c+1] : -CUDART_INF_F;
                if (j0 + JT <= SS) {
                    *(float2*)&sc[(ig*4+ii)*SS + j0c] = make_float2(v0, v1);
                } else {
                    if (j0c   < SS) sc[(ig*4+ii)*SS + j0c]   = v0;
                    if (j0c+1 < SS) sc[(ig*4+ii)*SS + j0c+1] = v1;
                }
            }
        }
        __syncthreads();

        // ----- softmax per row (16 warps over 32 rows) -----
        for (int r = warp; r < QT; r += 16) {
            float* row = sc + r*SS;
            float m = -CUDART_INF_F;
            for (int j = lane; j < jcap; j += 32) m = fmaxf(m, row[j]);
#pragma unroll
            for (int o = 16; o; o >>= 1) m = fmaxf(m, __shfl_xor_sync(0xffffffffu, m, o));
            float ssum = 0.f;
            for (int j = lane; j < jcap; j += 32) {
                float e = __expf(row[j] - m);
                row[j] = e;
                ssum += e;
            }
#pragma unroll
            for (int o = 16; o; o >>= 1) ssum += __shfl_xor_sync(0xffffffffu, ssum, o);
            float inv = 1.f / ssum;
            for (int j = lane; j < jcap; j += 32) row[j] *= inv;
        }
        __syncthreads();

        // ----- attn-mean accumulate into gmem (L2-resident) -----
        if (h == 0) {
            for (int i = 0; i < QT; i++) {
                float* dst = out_attn + abase + (size_t)i*SS;
                const float* src = sc + i*SS;
                for (int j = tid; j < SS; j += 512)
                    dst[j] = (j < jcap) ? src[j]*0.125f : 0.f;
            }
        } else {
            for (int i = 0; i < QT; i++) {
                float* dst = out_attn + abase + (size_t)i*SS;
                const float* src = sc + i*SS;
                for (int j = tid; j < jcap; j += 512)
                    dst[j] += src[j]*0.125f;
            }
        }

        // ----- ctx = P @ V  (1 row x 4 d per thread, float4 p loads) -----
        {
            const int i = tid >> 4;              // 32 rows
            const int dbase = (tid & 15) * 4;    // 16 d-groups of 4
            float a0 = 0.f, a1 = 0.f, a2 = 0.f, a3 = 0.f;
            for (int jt = 0; jt < ntile; jt++) {
                int j0 = jt * JT;
                __syncthreads();
                for (int idx = tid; idx < JT*DK; idx += 512) {
                    int j = j0 + (idx >> 6);
                    kvb[idx] = (j < SS) ? vg[(size_t)j*DK + (idx & 63)] : 0.f;
                }
                __syncthreads();
                int jlim = min(JT, jcap - j0);
                for (int jj = 0; jj < jlim; jj += 4) {
                    float4 p = *(const float4*)&sc[i*SS + j0 + jj];
                    float4 v0 = *(const float4*)&kvb[((jj+0) << 6) + dbase];
                    float4 v1 = *(const float4*)&kvb[((jj+1) << 6) + dbase];
                    float4 v2 = *(const float4*)&kvb[((jj+2) << 6) + dbase];
                    float4 v3 = *(const float4*)&kvb[((jj+3) << 6) + dbase];
                    a0 += p.x*v0.x + p.y*v1.x + p.z*v2.x + p.w*v3.x;
                    a1 += p.x*v0.y + p.y*v1.y + p.z*v2.y + p.w*v3.y;
                    a2 += p.x*v0.z + p.y*v1.z + p.z*v2.z + p.w*v3.z;
                    a3 += p.x*v0.w + p.y*v1.w + p.z*v2.w + p.w*v3.w;
                }
            }
            *(float4*)&g_ctx[((size_t)b*SS + i0 + i)*DD + h*DK + dbase] =
                make_float4(a0, a1, a2, a3);
        }
    }
}

// ---------------------------------------------------------------------------
// Kernel 3: output projection.  out = ctx @ wo + bo.  Same tiling as proj_qkv.
// ---------------------------------------------------------------------------
__global__ __launch_bounds__(256) void out_proj(
    const float* __restrict__ wo, const float* __restrict__ bo,
    float* __restrict__ out)
{
    __shared__ float Xs[32][132];
    __shared__ float Ws[32][68];

    const int m0 = blockIdx.x * 64;
    const int n0 = blockIdx.y * 128;
    const int tid = threadIdx.x;

    const int c8 = tid & 7, xr = tid >> 3;
    const int wc = tid & 63, wt = tid >> 6;
    const int ri = tid >> 4, ci = tid & 15;

    float acc[8][4] = {};

    for (int k0 = 0; k0 < DD; k0 += 32) {
#pragma unroll
        for (int rr = 0; rr < 4; rr++) {
            int r = xr + rr*32;
            float4 v = *(const float4*)&g_ctx[(size_t)(n0 + r)*DD + k0 + c8*4];
            Xs[c8*4+0][r] = v.x; Xs[c8*4+1][r] = v.y;
            Xs[c8*4+2][r] = v.z; Xs[c8*4+3][r] = v.w;
        }
#pragma unroll
        for (int tt = 0; tt < 8; tt++)
            Ws[wt + tt*4][wc] = wo[(size_t)(k0 + wt + tt*4)*DD + m0 + wc];
        __syncthreads();
#pragma unroll
        for (int t = 0; t < 32; t++) {
            float4 a0 = *(const float4*)&Xs[t][ri*8];
            float4 a1 = *(const float4*)&Xs[t][ri*8+4];
            float4 b4 = *(const float4*)&Ws[t][ci*4];
            float av[8] = {a0.x,a0.y,a0.z,a0.w,a1.x,a1.y,a1.z,a1.w};
            float bw[4] = {b4.x,b4.y,b4.z,b4.w};
#pragma unroll
            for (int i = 0; i < 8; i++)
#pragma unroll
                for (int j = 0; j < 4; j++)
                    acc[i][j] += av[i] * bw[j];
        }
        __syncthreads();
    }

    const float4 bb = *(const float4*)&bo[m0 + ci*4];
#pragma unroll
    for (int u = 0; u < 8; u++) {
        int n = n0 + ri*8 + u;
        float4 o = make_float4(acc[u][0]+bb.x, acc[u][1]+bb.y,
                               acc[u][2]+bb.z, acc[u][3]+bb.w);
        *(float4*)&out[(size_t)n*DD + m0 + ci*4] = o;
    }
}

// ---------------------------------------------------------------------------

static const int ATTN_SMEM = (QT*SS + 64*QTP + 64*JTP) * (int)sizeof(float); // 104448

extern "C" void kernel_launch(void* const* d_in, const int* in_sizes, int n_in,
                              void* d_out, int out_size) {
    const float* x  = (const float*)d_in[0];
    const float* wq = (const float*)d_in[1];
    const float* bq = (const float*)d_in[2];
    const float* wk = (const float*)d_in[3];
    const float* bk = (const float*)d_in[4];
    const float* wv = (const float*)d_in[5];
    const float* bv = (const float*)d_in[6];
    const float* wo = (const float*)d_in[7];
    const float* bo = (const float*)d_in[8];
    const float* rb = (const float*)d_in[9];

    float* out      = (float*)d_out;
    float* out_attn = out + (size_t)BB*SS*DD;

    // 1) QKV projections
    proj_qkv<<<dim3(DD/64, (BB*SS)/128, 3), 256>>>(x, wq, bq, wk, bk, wv, bv);

    // 2) attention
    cudaFuncSetAttribute(attn_kernel, cudaFuncAttributeMaxDynamicSharedMemorySize, ATTN_SMEM);
    attn_kernel<<<dim3(SS/QT, BB), 512, ATTN_SMEM>>>(rb, out_attn);

    // 3) output projection
    out_proj<<<dim3(DD/64, (BB*SS)/128), 256>>>(wo, bo, out);
}